// round 2
// baseline (speedup 1.0000x reference)
#include <cuda_runtime.h>

// Problem constants
#define NBATCH   131072
#define GDIM     9
#define CELLS    81            // 9*9
#define NWAVE    3
#define NB       3             // batch items per block
#define NTHREADS 256

// resp elements per block (staged in shared for coalesced flush)
#define RESP_PER_BLOCK (NB * CELLS * NWAVE)   // 729

__global__ __launch_bounds__(NTHREADS)
void photonic_kernel(const int*   __restrict__ grid,      // [B,9,9]
                     const float* __restrict__ nidx,      // [9,9]
                     const float* __restrict__ absorb,    // [9,9,3]
                     const float* __restrict__ ts_ptr,    // scalar
                     float* __restrict__ feats,           // [B,9,9,4]
                     float* __restrict__ resp)            // [B,9,9,3]
{
    __shared__ float s_mean[NB][CELLS];
    __shared__ float s_resp[RESP_PER_BLOCK];

    const int t       = threadIdx.x;
    const int local_b = t / CELLS;            // 0..2 for t<243
    const int cell    = t - local_b * CELLS;  // 0..80
    const int b       = blockIdx.x * NB + local_b;
    const bool active = (t < NB * CELLS) && (b < NBATCH);

    const float ts = __ldg(ts_ptr);

    float m = 0.0f, var = 0.0f;

    if (active) {
        const int   g  = __ldg(&grid[(long)b * CELLS + cell]);
        const float n  = __ldg(&nidx[cell]);

        // heights = BASE + ts*g   (fma-contracted both here and in XLA)
        const float heights = 1e-4f + ts * (float)g;
        const float path    = heights * n;

        const float d    = (1.0f - n) / (1.0f + n);
        const float frac = 1.0f - d * d;               // transmit fraction

        const float two_pi_path = 6.283185307179586f * path;

        const float lam0 = 6.5e-07f, lam1 = 5.5e-07f, lam2 = 4.5e-07f;

        float r0, r1, r2;
        {
            const float a0 = fabsf(__ldg(&absorb[cell * 3 + 0]));
            const float a1 = fabsf(__ldg(&absorb[cell * 3 + 1]));
            const float a2 = fabsf(__ldg(&absorb[cell * 3 + 2]));

            const float t0 = expf(-a0 * path);
            const float t1 = expf(-a1 * path);
            const float t2 = expf(-a2 * path);

            const float i0 = 0.5f * (1.0f + cosf(two_pi_path / lam0));
            const float i1 = 0.5f * (1.0f + cosf(two_pi_path / lam1));
            const float i2 = 0.5f * (1.0f + cosf(two_pi_path / lam2));

            r0 = frac * t0 * i0;
            r1 = frac * t1 * i1;
            r2 = frac * t2 * i2;
        }

        // spectral mean / unbiased var over the 3 wavelengths
        m = (r0 + r1 + r2) / 3.0f;
        const float e0 = r0 - m, e1 = r1 - m, e2 = r2 - m;
        var = (e0 * e0 + e1 * e1 + e2 * e2) * 0.5f;

        s_mean[local_b][cell] = m;

        const int roff = (local_b * CELLS + cell) * NWAVE;
        s_resp[roff + 0] = r0;
        s_resp[roff + 1] = r1;
        s_resp[roff + 2] = r2;
    }

    __syncthreads();

    // feats: [B,9,9,4] as one float4 per (b,cell) — perfectly coalesced
    if (active) {
        const int i = cell / GDIM;
        const int j = cell - i * GDIM;
        const float gx = (j < GDIM - 1) ? (s_mean[local_b][cell + 1]    - m) : 0.0f;
        const float gy = (i < GDIM - 1) ? (s_mean[local_b][cell + GDIM] - m) : 0.0f;
        reinterpret_cast<float4*>(feats)[(long)b * CELLS + cell] =
            make_float4(m, var, gx, gy);
    }

    // resp flush: linear coalesced scalar stores from shared
    {
        const long block_base = (long)blockIdx.x * RESP_PER_BLOCK;   // = b0*243
        const long resp_total = (long)NBATCH * CELLS * NWAVE;
        #pragma unroll
        for (int k = 0; k < (RESP_PER_BLOCK + NTHREADS - 1) / NTHREADS; k++) {
            const int idx = t + k * NTHREADS;
            if (idx < RESP_PER_BLOCK) {
                const long gidx = block_base + idx;
                if (gidx < resp_total) resp[gidx] = s_resp[idx];
            }
        }
    }
}

extern "C" void kernel_launch(void* const* d_in, const int* in_sizes, int n_in,
                              void* d_out, int out_size)
{
    const int*   grid_p = (const int*)  d_in[0];   // sudoku_grid [B,9,9] int32
    const float* nidx_p = (const float*)d_in[1];   // refractive_indices [9,9]
    const float* absb_p = (const float*)d_in[2];   // absorption_coeffs [9,9,3]
    const float* ts_p   = (const float*)d_in[3];   // thickness_scale scalar

    float* feats_p = (float*)d_out;                                   // [B,9,9,4]
    float* resp_p  = feats_p + (size_t)NBATCH * CELLS * 4;            // [B,9,9,3]

    const int nblocks = (NBATCH + NB - 1) / NB;
    photonic_kernel<<<nblocks, NTHREADS>>>(grid_p, nidx_p, absb_p, ts_p,
                                           feats_p, resp_p);
}

// round 5
// speedup vs baseline: 1.4846x; 1.4846x over previous
#include <cuda_runtime.h>

#define NBATCH   131072
#define GDIM     9
#define CELLS    81
#define NWAVE    3
#define NB       3              // batch items per iteration (243-thread mapping)
#define K_ITERS  16             // batch-triples per block -> 48 batches/block
#define NTHREADS 256
#define LUT_STRIDE 5            // r0,r1,r2,mean,var (stride 5: coprime w/ 32 banks)
#define LUT_ENTRIES (CELLS * 10)               // 810
#define LUT_FLOATS  (LUT_ENTRIES * LUT_STRIDE) // 4050 floats = 16.2 KB

// ---------------------------------------------------------------------------
// Single fused kernel:
//   Phase 1: each block builds the 810-entry (cell,g) LUT in shared memory,
//            using the EXACT f32 op sequence of the Round-2-passing kernel
//            => bit-identical resp/mean/var.
//   Phase 2: pure gather — 243 active threads map (3 batches x 81 cells),
//            K_ITERS iterations => 48 batches per block.
// ---------------------------------------------------------------------------
__global__ __launch_bounds__(NTHREADS)
void photonic_fused_kernel(const int*   __restrict__ grid,    // [B,81]
                           const float* __restrict__ nidx,    // [9,9]
                           const float* __restrict__ absorb,  // [9,9,3]
                           const float* __restrict__ ts_ptr,  // scalar
                           float*       __restrict__ feats,   // [B,81,4]
                           float*       __restrict__ resp)    // [B,81,3]
{
    __shared__ float s_lut[LUT_FLOATS];

    // ---- Phase 1: build LUT (810 entries over 256 threads) ----
    {
        const float ts = __ldg(ts_ptr);
        for (int e = threadIdx.x; e < LUT_ENTRIES; e += NTHREADS) {
            const int cell = e / 10;
            const int g    = e - cell * 10;

            const float n = __ldg(&nidx[cell]);

            const float heights = 1e-4f + ts * (float)g;
            const float path    = heights * n;

            const float d    = (1.0f - n) / (1.0f + n);
            const float frac = 1.0f - d * d;

            const float two_pi_path = 6.283185307179586f * path;

            const float a0 = fabsf(__ldg(&absorb[cell * 3 + 0]));
            const float a1 = fabsf(__ldg(&absorb[cell * 3 + 1]));
            const float a2 = fabsf(__ldg(&absorb[cell * 3 + 2]));

            const float t0 = expf(-a0 * path);
            const float t1 = expf(-a1 * path);
            const float t2 = expf(-a2 * path);

            const float i0 = 0.5f * (1.0f + cosf(two_pi_path / 6.5e-07f));
            const float i1 = 0.5f * (1.0f + cosf(two_pi_path / 5.5e-07f));
            const float i2 = 0.5f * (1.0f + cosf(two_pi_path / 4.5e-07f));

            const float r0 = frac * t0 * i0;
            const float r1 = frac * t1 * i1;
            const float r2 = frac * t2 * i2;

            const float m  = (r0 + r1 + r2) / 3.0f;
            const float e0 = r0 - m, e1 = r1 - m, e2 = r2 - m;
            const float var = (e0 * e0 + e1 * e1 + e2 * e2) * 0.5f;

            float* dst = &s_lut[e * LUT_STRIDE];
            dst[0] = r0; dst[1] = r1; dst[2] = r2; dst[3] = m; dst[4] = var;
        }
    }
    __syncthreads();

    // ---- Phase 2: gather ----
    const int t = threadIdx.x;
    if (t >= NB * CELLS) return;

    const int local_b = t / CELLS;
    const int cell    = t - local_b * CELLS;
    const int ci      = cell / GDIM;
    const int cj      = cell - ci * GDIM;
    const bool has_r  = (cj < GDIM - 1);
    const bool has_d  = (ci < GDIM - 1);
    const int  off_r  = has_r ? 1 : 0;       // safe in-bounds offsets
    const int  off_d  = has_d ? GDIM : 0;

    const long b_first = (long)blockIdx.x * (NB * K_ITERS) + local_b;

    #pragma unroll 4
    for (int k = 0; k < K_ITERS; k++) {
        const long b = b_first + (long)k * NB;
        if (b >= NBATCH) break;

        const int* grow = grid + b * CELLS;
        const int g  = __ldg(&grow[cell]);
        const int gr = __ldg(&grow[cell + off_r]);   // L1 hit (same lines)
        const int gd = __ldg(&grow[cell + off_d]);

        const float* e = &s_lut[(cell * 10 + g) * LUT_STRIDE];
        const float r0 = e[0], r1 = e[1], r2 = e[2], m = e[3], v = e[4];

        const float mr = s_lut[((cell + off_r) * 10 + gr) * LUT_STRIDE + 3];
        const float md = s_lut[((cell + off_d) * 10 + gd) * LUT_STRIDE + 3];
        const float gx = has_r ? (mr - m) : 0.0f;
        const float gy = has_d ? (md - m) : 0.0f;

        reinterpret_cast<float4*>(feats)[b * CELLS + cell] =
            make_float4(m, v, gx, gy);

        const long ro = (b * CELLS + cell) * NWAVE;
        resp[ro + 0] = r0;
        resp[ro + 1] = r1;
        resp[ro + 2] = r2;
    }
}

extern "C" void kernel_launch(void* const* d_in, const int* in_sizes, int n_in,
                              void* d_out, int out_size)
{
    const int*   grid_p = (const int*)  d_in[0];   // sudoku_grid [B,9,9] int32
    const float* nidx_p = (const float*)d_in[1];   // refractive_indices [9,9]
    const float* absb_p = (const float*)d_in[2];   // absorption_coeffs [9,9,3]
    const float* ts_p   = (const float*)d_in[3];   // thickness_scale scalar

    float* feats_p = (float*)d_out;                            // [B,9,9,4]
    float* resp_p  = feats_p + (size_t)NBATCH * CELLS * 4;     // [B,9,9,3]

    const int batches_per_block = NB * K_ITERS;                // 48
    const int nblocks = (NBATCH + batches_per_block - 1) / batches_per_block;
    photonic_fused_kernel<<<nblocks, NTHREADS>>>(grid_p, nidx_p, absb_p, ts_p,
                                                 feats_p, resp_p);
}